// round 1
// baseline (speedup 1.0000x reference)
#include <cuda_runtime.h>
#include <math.h>

#define NN 50000
#define EE 800000
#define GG 256
#define DD 128
#define FF 1792   // 14*128
#define BN_EPS 1e-5f

// ---------------- scratch (device globals; no allocation allowed) ----------------
__device__ float g_z[(size_t)NN * DD];      // z = h + agg
__device__ float g_t1[(size_t)NN * DD];     // z @ W1 + b1 (pre-BN)
__device__ float g_h[(size_t)NN * DD];      // layer output h
__device__ float g_feat[(size_t)GG * FF];   // readout features [G,1792]
__device__ float g_feat2[(size_t)GG * FF];  // after MLP layer 1
__device__ float g_sum[DD];
__device__ float g_sqsum[DD];
__device__ float g_scale[DD];
__device__ float g_shift[DD];
__device__ int   g_starts[GG + 1];

// ---------------- graph boundaries (batch is sorted) ----------------
__global__ void k_starts(const int* __restrict__ batch) {
    int i = blockIdx.x * blockDim.x + threadIdx.x;
    if (i >= NN) return;
    int b = batch[i];
    if (i == 0) {
        for (int g = 0; g <= b; g++) g_starts[g] = 0;
    } else {
        int pb = batch[i - 1];
        if (pb != b) for (int g = pb + 1; g <= b; g++) g_starts[g] = i;
    }
    if (i == NN - 1) {
        for (int g = b + 1; g <= GG; g++) g_starts[g] = NN;
    }
}

// ---------------- z = h_in (vectorized copy) ----------------
__global__ void k_copy(const float* __restrict__ src) {
    int i = blockIdx.x * blockDim.x + threadIdx.x;
    const int n4 = NN * DD / 4;
    if (i < n4) reinterpret_cast<float4*>(g_z)[i] = reinterpret_cast<const float4*>(src)[i];
}

// ---------------- scatter-add: z[dst] += h[src]  (one warp per edge) ----------------
__global__ void k_scatter(const float* __restrict__ hin,
                          const int* __restrict__ src,
                          const int* __restrict__ dst) {
    int warp = (blockIdx.x * blockDim.x + threadIdx.x) >> 5;
    if (warp >= EE) return;
    int lane = threadIdx.x & 31;
    int s = src[warp];
    int d = dst[warp];
    float4 v = *reinterpret_cast<const float4*>(hin + (size_t)s * DD + lane * 4);
    float* zp = g_z + (size_t)d * DD + lane * 4;
    atomicAdd(zp + 0, v.x);
    atomicAdd(zp + 1, v.y);
    atomicAdd(zp + 2, v.z);
    atomicAdd(zp + 3, v.w);
}

// ---------------- main GEMM: [N,128] @ [128,128] + bias, optional BN+relu prologue,
//                  optional relu epilogue. BM=128, BK=16, 256 thr, 8x8 microtile ----
template <bool BN_PRE, bool RELU_OUT>
__global__ void __launch_bounds__(256, 2)
k_gemm128(const float* __restrict__ A, const float* __restrict__ W,
          const float* __restrict__ bias, float* __restrict__ C) {
    __shared__ float As[2][16][128];  // [k][row]
    __shared__ float Bs[2][16][128];  // [k][col]
    const int tid = threadIdx.x;
    const int tx = tid & 15, ty = tid >> 4;
    const int row0 = blockIdx.x * 128;

    float acc[8][8];
#pragma unroll
    for (int i = 0; i < 8; i++)
#pragma unroll
        for (int j = 0; j < 8; j++) acc[i][j] = 0.f;

    float4 ra[2], rb[2];

    auto ldg = [&](int k0) {
#pragma unroll
        for (int i = 0; i < 2; i++) {
            int v = tid + 256 * i;
            int r = v >> 2, kq = (v & 3) * 4;
            int gr = row0 + r;
            float4 val = make_float4(0.f, 0.f, 0.f, 0.f);
            if (gr < NN) val = *reinterpret_cast<const float4*>(A + (size_t)gr * DD + k0 + kq);
            if (BN_PRE) {
                float4 sc = *reinterpret_cast<const float4*>(g_scale + k0 + kq);
                float4 sh = *reinterpret_cast<const float4*>(g_shift + k0 + kq);
                val.x = fmaxf(fmaf(val.x, sc.x, sh.x), 0.f);
                val.y = fmaxf(fmaf(val.y, sc.y, sh.y), 0.f);
                val.z = fmaxf(fmaf(val.z, sc.z, sh.z), 0.f);
                val.w = fmaxf(fmaf(val.w, sc.w, sh.w), 0.f);
            }
            ra[i] = val;
            int kr = v >> 5, c4 = (v & 31) * 4;
            rb[i] = *reinterpret_cast<const float4*>(W + (size_t)(k0 + kr) * DD + c4);
        }
    };
    auto sts = [&](int s) {
#pragma unroll
        for (int i = 0; i < 2; i++) {
            int v = tid + 256 * i;
            int r = v >> 2, kq = (v & 3) * 4;
            As[s][kq + 0][r] = ra[i].x;
            As[s][kq + 1][r] = ra[i].y;
            As[s][kq + 2][r] = ra[i].z;
            As[s][kq + 3][r] = ra[i].w;
            int kr = v >> 5, c4 = (v & 31) * 4;
            *reinterpret_cast<float4*>(&Bs[s][kr][c4]) = rb[i];
        }
    };

    ldg(0);
    sts(0);
    __syncthreads();
    int s = 0;
#pragma unroll
    for (int t = 0; t < 8; t++) {
        if (t < 7) ldg((t + 1) * 16);
#pragma unroll
        for (int kk = 0; kk < 16; kk++) {
            float a[8], b[8];
            *reinterpret_cast<float4*>(a)     = *reinterpret_cast<const float4*>(&As[s][kk][ty * 8]);
            *reinterpret_cast<float4*>(a + 4) = *reinterpret_cast<const float4*>(&As[s][kk][ty * 8 + 4]);
            *reinterpret_cast<float4*>(b)     = *reinterpret_cast<const float4*>(&Bs[s][kk][tx * 8]);
            *reinterpret_cast<float4*>(b + 4) = *reinterpret_cast<const float4*>(&Bs[s][kk][tx * 8 + 4]);
#pragma unroll
            for (int i = 0; i < 8; i++)
#pragma unroll
                for (int j = 0; j < 8; j++) acc[i][j] = fmaf(a[i], b[j], acc[i][j]);
        }
        if (t < 7) sts(s ^ 1);
        __syncthreads();
        s ^= 1;
    }

    float bb[8];
#pragma unroll
    for (int j = 0; j < 8; j++) bb[j] = bias[tx * 8 + j];
#pragma unroll
    for (int i = 0; i < 8; i++) {
        int gr = row0 + ty * 8 + i;
        if (gr < NN) {
            float4 o0, o1;
            o0.x = acc[i][0] + bb[0]; o0.y = acc[i][1] + bb[1];
            o0.z = acc[i][2] + bb[2]; o0.w = acc[i][3] + bb[3];
            o1.x = acc[i][4] + bb[4]; o1.y = acc[i][5] + bb[5];
            o1.z = acc[i][6] + bb[6]; o1.w = acc[i][7] + bb[7];
            if (RELU_OUT) {
                o0.x = fmaxf(o0.x, 0.f); o0.y = fmaxf(o0.y, 0.f);
                o0.z = fmaxf(o0.z, 0.f); o0.w = fmaxf(o0.w, 0.f);
                o1.x = fmaxf(o1.x, 0.f); o1.y = fmaxf(o1.y, 0.f);
                o1.z = fmaxf(o1.z, 0.f); o1.w = fmaxf(o1.w, 0.f);
            }
            float* cp = C + (size_t)gr * DD + tx * 8;
            *reinterpret_cast<float4*>(cp)     = o0;
            *reinterpret_cast<float4*>(cp + 4) = o1;
        }
    }
}

// ---------------- column sums/sumsq of t1 for batchnorm ----------------
__global__ void k_stats(const float* __restrict__ t1) {
    __shared__ float ss[256], sq[256];
    int col = threadIdx.x & 127;
    int ph = threadIdx.x >> 7;
    float s = 0.f, q = 0.f;
    for (int r = blockIdx.x * 2 + ph; r < NN; r += gridDim.x * 2) {
        float v = t1[(size_t)r * DD + col];
        s += v;
        q += v * v;
    }
    ss[threadIdx.x] = s;
    sq[threadIdx.x] = q;
    __syncthreads();
    if (threadIdx.x < 128) {
        s = ss[threadIdx.x] + ss[threadIdx.x + 128];
        q = sq[threadIdx.x] + sq[threadIdx.x + 128];
        atomicAdd(&g_sum[col], s);
        atomicAdd(&g_sqsum[col], q);
    }
}

__global__ void k_bnfin(const float* __restrict__ gamma, const float* __restrict__ beta) {
    int c = threadIdx.x;
    float m = g_sum[c] * (1.f / NN);
    float var = g_sqsum[c] * (1.f / NN) - m * m;
    float sc = gamma[c] * rsqrtf(var + BN_EPS);
    g_scale[c] = sc;
    g_shift[c] = beta[c] - m * sc;
    g_sum[c] = 0.f;
    g_sqsum[c] = 0.f;
}

// ---------------- per-graph sum & max readout ----------------
__global__ void k_readout(const float* __restrict__ h, int layer) {
    int g = blockIdx.x;
    int c = threadIdx.x & 127;
    int ph = threadIdx.x >> 7;
    int s = g_starts[g], e = g_starts[g + 1];
    float sum = 0.f, mx = -3.402823466e38f;
#pragma unroll 4
    for (int r = s + ph; r < e; r += 2) {
        float v = h[(size_t)r * DD + c];
        sum += v;
        mx = fmaxf(mx, v);
    }
    __shared__ float rs[256];
    __shared__ float rm[256];
    rs[threadIdx.x] = sum;
    rm[threadIdx.x] = mx;
    __syncthreads();
    if (threadIdx.x < 128) {
        sum = rs[threadIdx.x] + rs[threadIdx.x + 128];
        mx = fmaxf(rm[threadIdx.x], rm[threadIdx.x + 128]);
        g_feat[(size_t)g * FF + layer * DD + c] = sum;          // segment sums (cols 0..895)
        g_feat[(size_t)g * FF + 7 * DD + layer * DD + c] = mx;  // segment maxs (cols 896..1791)
    }
}

// ---------------- MLP layer 1: [256,1792] @ [1792,1792] + bias, relu ----------------
__global__ void __launch_bounds__(256, 4)
k_gemm_mlp(const float* __restrict__ Afeat, const float* __restrict__ W,
           const float* __restrict__ bias, float* __restrict__ C) {
    __shared__ float As[2][16][32];
    __shared__ float Bs[2][16][128];
    const int tid = threadIdx.x;
    const int tx = tid & 15, ty = tid >> 4;
    const int row0 = blockIdx.y * 32;
    const int col0 = blockIdx.x * 128;

    float acc[2][8];
#pragma unroll
    for (int i = 0; i < 2; i++)
#pragma unroll
        for (int j = 0; j < 8; j++) acc[i][j] = 0.f;

    float4 ra;
    float4 rb[2];

    auto ldg = [&](int k0) {
        if (tid < 128) {
            int r = tid >> 2, kq = (tid & 3) * 4;
            ra = *reinterpret_cast<const float4*>(Afeat + (size_t)(row0 + r) * FF + k0 + kq);
        }
#pragma unroll
        for (int i = 0; i < 2; i++) {
            int v = tid + 256 * i;
            int kr = v >> 5, c4 = (v & 31) * 4;
            rb[i] = *reinterpret_cast<const float4*>(W + (size_t)(k0 + kr) * FF + col0 + c4);
        }
    };
    auto sts = [&](int s) {
        if (tid < 128) {
            int r = tid >> 2, kq = (tid & 3) * 4;
            As[s][kq + 0][r] = ra.x;
            As[s][kq + 1][r] = ra.y;
            As[s][kq + 2][r] = ra.z;
            As[s][kq + 3][r] = ra.w;
        }
#pragma unroll
        for (int i = 0; i < 2; i++) {
            int v = tid + 256 * i;
            int kr = v >> 5, c4 = (v & 31) * 4;
            *reinterpret_cast<float4*>(&Bs[s][kr][c4]) = rb[i];
        }
    };

    ldg(0);
    sts(0);
    __syncthreads();
    int s = 0;
    const int NT = FF / 16;  // 112
    for (int t = 0; t < NT; t++) {
        if (t < NT - 1) ldg((t + 1) * 16);
#pragma unroll
        for (int kk = 0; kk < 16; kk++) {
            float a0 = As[s][kk][ty * 2], a1 = As[s][kk][ty * 2 + 1];
            float b[8];
            *reinterpret_cast<float4*>(b)     = *reinterpret_cast<const float4*>(&Bs[s][kk][tx * 8]);
            *reinterpret_cast<float4*>(b + 4) = *reinterpret_cast<const float4*>(&Bs[s][kk][tx * 8 + 4]);
#pragma unroll
            for (int j = 0; j < 8; j++) {
                acc[0][j] = fmaf(a0, b[j], acc[0][j]);
                acc[1][j] = fmaf(a1, b[j], acc[1][j]);
            }
        }
        if (t < NT - 1) sts(s ^ 1);
        __syncthreads();
        s ^= 1;
    }
#pragma unroll
    for (int i = 0; i < 2; i++) {
        int gr = row0 + ty * 2 + i;
        float* cp = C + (size_t)gr * FF + col0 + tx * 8;
#pragma unroll
        for (int j = 0; j < 8; j++) {
            float v = acc[i][j] + bias[col0 + tx * 8 + j];
            cp[j] = fmaxf(v, 0.f);
        }
    }
}

// ---------------- head: logits + sigmoid ----------------
__global__ void k_head(const float* __restrict__ Wl2, const float* __restrict__ bl2,
                       float* __restrict__ out) {
    int g = blockIdx.x;
    float p = 0.f;
    for (int k = threadIdx.x; k < FF; k += 256)
        p += g_feat2[(size_t)g * FF + k] * Wl2[k];
    __shared__ float red[256];
    red[threadIdx.x] = p;
    __syncthreads();
    for (int off = 128; off > 0; off >>= 1) {
        if (threadIdx.x < off) red[threadIdx.x] += red[threadIdx.x + off];
        __syncthreads();
    }
    if (threadIdx.x == 0) {
        float l = red[0] + bl2[0];
        out[g] = 1.f / (1.f + expf(-l));  // sigmoid output
        out[GG + g] = l;                  // raw logit output
    }
}

// ---------------- launch ----------------
extern "C" void kernel_launch(void* const* d_in, const int* in_sizes, int n_in,
                              void* d_out, int out_size) {
    const float* x     = (const float*)d_in[0];
    const int*   ei    = (const int*)d_in[1];
    const int*   batch = (const int*)d_in[2];
    const float* W1    = (const float*)d_in[3];
    const float* b1    = (const float*)d_in[4];
    const float* gamma = (const float*)d_in[5];
    const float* beta  = (const float*)d_in[6];
    const float* W2    = (const float*)d_in[7];
    const float* b2    = (const float*)d_in[8];
    const float* Wl1   = (const float*)d_in[9];
    const float* bl1   = (const float*)d_in[10];
    const float* Wl2   = (const float*)d_in[11];
    const float* bl2   = (const float*)d_in[12];
    float* out = (float*)d_out;

    float *zp, *t1p, *hp, *featp, *feat2p;
    cudaGetSymbolAddress((void**)&zp, g_z);
    cudaGetSymbolAddress((void**)&t1p, g_t1);
    cudaGetSymbolAddress((void**)&hp, g_h);
    cudaGetSymbolAddress((void**)&featp, g_feat);
    cudaGetSymbolAddress((void**)&feat2p, g_feat2);

    k_starts<<<(NN + 255) / 256, 256>>>(batch);

    const float* hin = x;
    for (int l = 0; l < 7; l++) {
        k_copy<<<(NN * DD / 4 + 255) / 256, 256>>>(hin);
        k_scatter<<<(EE * 32) / 256, 256>>>(hin, ei, ei + EE);
        k_gemm128<false, false><<<(NN + 127) / 128, 256>>>(zp, W1 + (size_t)l * DD * DD,
                                                           b1 + l * DD, t1p);
        k_stats<<<512, 256>>>(t1p);
        k_bnfin<<<1, 128>>>(gamma + l * DD, beta + l * DD);
        k_gemm128<true, true><<<(NN + 127) / 128, 256>>>(t1p, W2 + (size_t)l * DD * DD,
                                                         b2 + l * DD, hp);
        k_readout<<<GG, 256>>>(hp, l);
        hin = hp;
    }
    k_gemm_mlp<<<dim3(FF / 128, GG / 32), 256>>>(featp, Wl1, bl1, feat2p);
    k_head<<<GG, 256>>>(Wl2, bl2, out);
}

// round 3
// speedup vs baseline: 1.9369x; 1.9369x over previous
#include <cuda_runtime.h>
#include <math.h>

#define NN 50000
#define EE 800000
#define GG 256
#define DD 128
#define FF 1792   // 14*128
#define BN_EPS 1e-5f
#define NB_SCAN 196  // ceil(NN/256)

// ---------------- scratch (device globals) ----------------
__device__ float g_z[(size_t)NN * DD];
__device__ float g_t1[(size_t)NN * DD];
__device__ float g_h[(size_t)NN * DD];
__device__ float g_feat[(size_t)GG * FF];
__device__ float g_feat2[(size_t)GG * FF];
__device__ float g_sum[DD];
__device__ float g_sqsum[DD];
__device__ float g_scale[DD];
__device__ float g_shift[DD];
__device__ int   g_starts[GG + 1];
// CSR scratch
__device__ int g_deg[NN];
__device__ int g_cursor[NN];
__device__ int g_rowptr[NN + 1];
__device__ int g_esrc[EE];
__device__ int g_bsum[256];

// ---------------- graph boundaries (batch is sorted) ----------------
__global__ void k_starts(const int* __restrict__ batch) {
    int i = blockIdx.x * blockDim.x + threadIdx.x;
    if (i >= NN) return;
    int b = batch[i];
    if (i == 0) {
        for (int g = 0; g <= b; g++) g_starts[g] = 0;
    } else {
        int pb = batch[i - 1];
        if (pb != b) for (int g = pb + 1; g <= b; g++) g_starts[g] = i;
    }
    if (i == NN - 1) {
        for (int g = b + 1; g <= GG; g++) g_starts[g] = NN;
    }
}

// ---------------- CSR build ----------------
__global__ void k_zero_csr() {
    int i = blockIdx.x * blockDim.x + threadIdx.x;
    if (i < NN) { g_deg[i] = 0; g_cursor[i] = 0; }
}

__global__ void k_hist(const int* __restrict__ dst) {
    int e = blockIdx.x * blockDim.x + threadIdx.x;
    if (e < EE) atomicAdd(&g_deg[dst[e]], 1);
}

__global__ void k_scan1() {
    __shared__ int sh[256];
    int t = threadIdx.x;
    int i = blockIdx.x * 256 + t;
    int v = (i < NN) ? g_deg[i] : 0;
    sh[t] = v;
    __syncthreads();
#pragma unroll
    for (int off = 1; off < 256; off <<= 1) {
        int a = (t >= off) ? sh[t - off] : 0;
        __syncthreads();
        sh[t] += a;
        __syncthreads();
    }
    if (i < NN) g_rowptr[i] = sh[t] - v;  // exclusive within block
    if (t == 255) g_bsum[blockIdx.x] = sh[255];
}

__global__ void k_scan2() {
    __shared__ int sh[256];
    int t = threadIdx.x;
    int v = (t < NB_SCAN) ? g_bsum[t] : 0;
    sh[t] = v;
    __syncthreads();
#pragma unroll
    for (int off = 1; off < 256; off <<= 1) {
        int a = (t >= off) ? sh[t - off] : 0;
        __syncthreads();
        sh[t] += a;
        __syncthreads();
    }
    if (t < NB_SCAN) g_bsum[t] = sh[t] - v;  // exclusive
}

__global__ void k_scan3() {
    int i = blockIdx.x * blockDim.x + threadIdx.x;
    if (i < NN) g_rowptr[i] += g_bsum[i >> 8];
    if (i == 0) g_rowptr[NN] = EE;
}

__global__ void k_fill(const int* __restrict__ src, const int* __restrict__ dst) {
    int e = blockIdx.x * blockDim.x + threadIdx.x;
    if (e >= EE) return;
    int d = dst[e];
    int pos = atomicAdd(&g_cursor[d], 1);
    g_esrc[g_rowptr[d] + pos] = src[e];
}

// ---------------- aggregation: z[n] = h[n] + sum_{j in in(n)} h[src_j] ------
// one warp per node, lane covers float4 of the 128-wide row
__global__ void k_agg(const float* __restrict__ h) {
    int warp = (blockIdx.x * blockDim.x + threadIdx.x) >> 5;
    if (warp >= NN) return;
    int lane = threadIdx.x & 31;
    const float4* __restrict__ h4 = reinterpret_cast<const float4*>(h);
    float4 acc = h4[(size_t)warp * 32 + lane];
    int s = g_rowptr[warp], e = g_rowptr[warp + 1];
    int j = s;
    for (; j + 4 <= e; j += 4) {
        int i0 = g_esrc[j], i1 = g_esrc[j + 1], i2 = g_esrc[j + 2], i3 = g_esrc[j + 3];
        float4 v0 = h4[(size_t)i0 * 32 + lane];
        float4 v1 = h4[(size_t)i1 * 32 + lane];
        float4 v2 = h4[(size_t)i2 * 32 + lane];
        float4 v3 = h4[(size_t)i3 * 32 + lane];
        acc.x += v0.x + v1.x + v2.x + v3.x;
        acc.y += v0.y + v1.y + v2.y + v3.y;
        acc.z += v0.z + v1.z + v2.z + v3.z;
        acc.w += v0.w + v1.w + v2.w + v3.w;
    }
    for (; j < e; j++) {
        int i0 = g_esrc[j];
        float4 v0 = h4[(size_t)i0 * 32 + lane];
        acc.x += v0.x; acc.y += v0.y; acc.z += v0.z; acc.w += v0.w;
    }
    reinterpret_cast<float4*>(g_z)[(size_t)warp * 32 + lane] = acc;
}

// ---------------- GEMM: [N,128] @ [128,128] + bias; BM=64, BN=128, BK=16 ----
// 256 threads, 4x8 microtile, 3 CTAs/SM target
template <bool BN_PRE, bool RELU_OUT>
__global__ void __launch_bounds__(256, 3)
k_gemm64(const float* __restrict__ A, const float* __restrict__ W,
         const float* __restrict__ bias, float* __restrict__ C) {
    __shared__ float As[2][16][64];
    __shared__ float Bs[2][16][128];
    const int tid = threadIdx.x;
    const int tx = tid & 15, ty = tid >> 4;
    const int row0 = blockIdx.x * 64;

    float acc[4][8];
#pragma unroll
    for (int i = 0; i < 4; i++)
#pragma unroll
        for (int j = 0; j < 8; j++) acc[i][j] = 0.f;

    float4 ra, rb[2];

    auto ldg = [&](int k0) {
        {
            int r = tid >> 2, kq = (tid & 3) * 4;
            int gr = row0 + r;
            float4 val = make_float4(0.f, 0.f, 0.f, 0.f);
            if (gr < NN) val = *reinterpret_cast<const float4*>(A + (size_t)gr * DD + k0 + kq);
            if (BN_PRE) {
                float4 sc = *reinterpret_cast<const float4*>(g_scale + k0 + kq);
                float4 sh = *reinterpret_cast<const float4*>(g_shift + k0 + kq);
                val.x = fmaxf(fmaf(val.x, sc.x, sh.x), 0.f);
                val.y = fmaxf(fmaf(val.y, sc.y, sh.y), 0.f);
                val.z = fmaxf(fmaf(val.z, sc.z, sh.z), 0.f);
                val.w = fmaxf(fmaf(val.w, sc.w, sh.w), 0.f);
            }
            ra = val;
        }
#pragma unroll
        for (int i = 0; i < 2; i++) {
            int v = tid + 256 * i;
            int kr = v >> 5, c4 = (v & 31) * 4;
            rb[i] = *reinterpret_cast<const float4*>(W + (size_t)(k0 + kr) * DD + c4);
        }
    };
    auto sts = [&](int s) {
        int r = tid >> 2, kq = (tid & 3) * 4;
        As[s][kq + 0][r] = ra.x;
        As[s][kq + 1][r] = ra.y;
        As[s][kq + 2][r] = ra.z;
        As[s][kq + 3][r] = ra.w;
#pragma unroll
        for (int i = 0; i < 2; i++) {
            int v = tid + 256 * i;
            int kr = v >> 5, c4 = (v & 31) * 4;
            *reinterpret_cast<float4*>(&Bs[s][kr][c4]) = rb[i];
        }
    };

    ldg(0);
    sts(0);
    __syncthreads();
    int s = 0;
#pragma unroll
    for (int t = 0; t < 8; t++) {
        if (t < 7) ldg((t + 1) * 16);
#pragma unroll
        for (int kk = 0; kk < 16; kk++) {
            float a[4], b[8];
            *reinterpret_cast<float4*>(a)     = *reinterpret_cast<const float4*>(&As[s][kk][ty * 4]);
            *reinterpret_cast<float4*>(b)     = *reinterpret_cast<const float4*>(&Bs[s][kk][tx * 8]);
            *reinterpret_cast<float4*>(b + 4) = *reinterpret_cast<const float4*>(&Bs[s][kk][tx * 8 + 4]);
#pragma unroll
            for (int i = 0; i < 4; i++)
#pragma unroll
                for (int j = 0; j < 8; j++) acc[i][j] = fmaf(a[i], b[j], acc[i][j]);
        }
        if (t < 7) sts(s ^ 1);
        __syncthreads();
        s ^= 1;
    }

    float bb[8];
#pragma unroll
    for (int j = 0; j < 8; j++) bb[j] = bias[tx * 8 + j];
#pragma unroll
    for (int i = 0; i < 4; i++) {
        int gr = row0 + ty * 4 + i;
        if (gr < NN) {
            float4 o0, o1;
            o0.x = acc[i][0] + bb[0]; o0.y = acc[i][1] + bb[1];
            o0.z = acc[i][2] + bb[2]; o0.w = acc[i][3] + bb[3];
            o1.x = acc[i][4] + bb[4]; o1.y = acc[i][5] + bb[5];
            o1.z = acc[i][6] + bb[6]; o1.w = acc[i][7] + bb[7];
            if (RELU_OUT) {
                o0.x = fmaxf(o0.x, 0.f); o0.y = fmaxf(o0.y, 0.f);
                o0.z = fmaxf(o0.z, 0.f); o0.w = fmaxf(o0.w, 0.f);
                o1.x = fmaxf(o1.x, 0.f); o1.y = fmaxf(o1.y, 0.f);
                o1.z = fmaxf(o1.z, 0.f); o1.w = fmaxf(o1.w, 0.f);
            }
            float* cp = C + (size_t)gr * DD + tx * 8;
            *reinterpret_cast<float4*>(cp)     = o0;
            *reinterpret_cast<float4*>(cp + 4) = o1;
        }
    }
}

// ---------------- column sums/sumsq of t1 for batchnorm ----------------
__global__ void k_stats(const float* __restrict__ t1) {
    __shared__ float ss[256], sq[256];
    int col = threadIdx.x & 127;
    int ph = threadIdx.x >> 7;
    float s = 0.f, q = 0.f;
    for (int r = blockIdx.x * 2 + ph; r < NN; r += gridDim.x * 2) {
        float v = t1[(size_t)r * DD + col];
        s += v;
        q += v * v;
    }
    ss[threadIdx.x] = s;
    sq[threadIdx.x] = q;
    __syncthreads();
    if (threadIdx.x < 128) {
        s = ss[threadIdx.x] + ss[threadIdx.x + 128];
        q = sq[threadIdx.x] + sq[threadIdx.x + 128];
        atomicAdd(&g_sum[col], s);
        atomicAdd(&g_sqsum[col], q);
    }
}

__global__ void k_bnfin(const float* __restrict__ gamma, const float* __restrict__ beta) {
    int c = threadIdx.x;
    float m = g_sum[c] * (1.f / NN);
    float var = g_sqsum[c] * (1.f / NN) - m * m;
    float sc = gamma[c] * rsqrtf(var + BN_EPS);
    g_scale[c] = sc;
    g_shift[c] = beta[c] - m * sc;
    g_sum[c] = 0.f;
    g_sqsum[c] = 0.f;
}

// ---------------- per-graph sum & max readout ----------------
__global__ void k_readout(const float* __restrict__ h, int layer) {
    int g = blockIdx.x;
    int c = threadIdx.x & 127;
    int ph = threadIdx.x >> 7;
    int s = g_starts[g], e = g_starts[g + 1];
    float sum = 0.f, mx = -3.402823466e38f;
#pragma unroll 4
    for (int r = s + ph; r < e; r += 2) {
        float v = h[(size_t)r * DD + c];
        sum += v;
        mx = fmaxf(mx, v);
    }
    __shared__ float rs[256];
    __shared__ float rm[256];
    rs[threadIdx.x] = sum;
    rm[threadIdx.x] = mx;
    __syncthreads();
    if (threadIdx.x < 128) {
        sum = rs[threadIdx.x] + rs[threadIdx.x + 128];
        mx = fmaxf(rm[threadIdx.x], rm[threadIdx.x + 128]);
        g_feat[(size_t)g * FF + layer * DD + c] = sum;
        g_feat[(size_t)g * FF + 7 * DD + layer * DD + c] = mx;
    }
}

// ---------------- MLP layer 1: [256,1792] @ [1792,1792] + bias, relu ----------------
__global__ void __launch_bounds__(256, 4)
k_gemm_mlp(const float* __restrict__ Afeat, const float* __restrict__ W,
           const float* __restrict__ bias, float* __restrict__ C) {
    __shared__ float As[2][16][32];
    __shared__ float Bs[2][16][128];
    const int tid = threadIdx.x;
    const int tx = tid & 15, ty = tid >> 4;
    const int row0 = blockIdx.y * 32;
    const int col0 = blockIdx.x * 128;

    float acc[2][8];
#pragma unroll
    for (int i = 0; i < 2; i++)
#pragma unroll
        for (int j = 0; j < 8; j++) acc[i][j] = 0.f;

    float4 ra;
    float4 rb[2];

    auto ldg = [&](int k0) {
        if (tid < 128) {
            int r = tid >> 2, kq = (tid & 3) * 4;
            ra = *reinterpret_cast<const float4*>(Afeat + (size_t)(row0 + r) * FF + k0 + kq);
        }
#pragma unroll
        for (int i = 0; i < 2; i++) {
            int v = tid + 256 * i;
            int kr = v >> 5, c4 = (v & 31) * 4;
            rb[i] = *reinterpret_cast<const float4*>(W + (size_t)(k0 + kr) * FF + col0 + c4);
        }
    };
    auto sts = [&](int s) {
        if (tid < 128) {
            int r = tid >> 2, kq = (tid & 3) * 4;
            As[s][kq + 0][r] = ra.x;
            As[s][kq + 1][r] = ra.y;
            As[s][kq + 2][r] = ra.z;
            As[s][kq + 3][r] = ra.w;
        }
#pragma unroll
        for (int i = 0; i < 2; i++) {
            int v = tid + 256 * i;
            int kr = v >> 5, c4 = (v & 31) * 4;
            *reinterpret_cast<float4*>(&Bs[s][kr][c4]) = rb[i];
        }
    };

    ldg(0);
    sts(0);
    __syncthreads();
    int s = 0;
    const int NT = FF / 16;  // 112
    for (int t = 0; t < NT; t++) {
        if (t < NT - 1) ldg((t + 1) * 16);
#pragma unroll
        for (int kk = 0; kk < 16; kk++) {
            float a0 = As[s][kk][ty * 2], a1 = As[s][kk][ty * 2 + 1];
            float b[8];
            *reinterpret_cast<float4*>(b)     = *reinterpret_cast<const float4*>(&Bs[s][kk][tx * 8]);
            *reinterpret_cast<float4*>(b + 4) = *reinterpret_cast<const float4*>(&Bs[s][kk][tx * 8 + 4]);
#pragma unroll
            for (int j = 0; j < 8; j++) {
                acc[0][j] = fmaf(a0, b[j], acc[0][j]);
                acc[1][j] = fmaf(a1, b[j], acc[1][j]);
            }
        }
        if (t < NT - 1) sts(s ^ 1);
        __syncthreads();
        s ^= 1;
    }
#pragma unroll
    for (int i = 0; i < 2; i++) {
        int gr = row0 + ty * 2 + i;
        float* cp = C + (size_t)gr * FF + col0 + tx * 8;
#pragma unroll
        for (int j = 0; j < 8; j++) {
            float v = acc[i][j] + bias[col0 + tx * 8 + j];
            cp[j] = fmaxf(v, 0.f);
        }
    }
}

// ---------------- head: logits + sigmoid ----------------
__global__ void k_head(const float* __restrict__ Wl2, const float* __restrict__ bl2,
                       float* __restrict__ out) {
    int g = blockIdx.x;
    float p = 0.f;
    for (int k = threadIdx.x; k < FF; k += 256)
        p += g_feat2[(size_t)g * FF + k] * Wl2[k];
    __shared__ float red[256];
    red[threadIdx.x] = p;
    __syncthreads();
    for (int off = 128; off > 0; off >>= 1) {
        if (threadIdx.x < off) red[threadIdx.x] += red[threadIdx.x + off];
        __syncthreads();
    }
    if (threadIdx.x == 0) {
        float l = red[0] + bl2[0];
        out[g] = 1.f / (1.f + expf(-l));
        out[GG + g] = l;
    }
}

// ---------------- launch ----------------
extern "C" void kernel_launch(void* const* d_in, const int* in_sizes, int n_in,
                              void* d_out, int out_size) {
    const float* x     = (const float*)d_in[0];
    const int*   ei    = (const int*)d_in[1];
    const int*   batch = (const int*)d_in[2];
    const float* W1    = (const float*)d_in[3];
    const float* b1    = (const float*)d_in[4];
    const float* gamma = (const float*)d_in[5];
    const float* beta  = (const float*)d_in[6];
    const float* W2    = (const float*)d_in[7];
    const float* b2    = (const float*)d_in[8];
    const float* Wl1   = (const float*)d_in[9];
    const float* bl1   = (const float*)d_in[10];
    const float* Wl2   = (const float*)d_in[11];
    const float* bl2   = (const float*)d_in[12];
    float* out = (float*)d_out;

    const int* src = ei;
    const int* dst = ei + EE;

    float *zp, *t1p, *hp, *featp, *feat2p;
    cudaGetSymbolAddress((void**)&zp, g_z);
    cudaGetSymbolAddress((void**)&t1p, g_t1);
    cudaGetSymbolAddress((void**)&hp, g_h);
    cudaGetSymbolAddress((void**)&featp, g_feat);
    cudaGetSymbolAddress((void**)&feat2p, g_feat2);

    k_starts<<<(NN + 255) / 256, 256>>>(batch);

    // CSR build (per replay; race order only perturbs fp sum order)
    k_zero_csr<<<(NN + 255) / 256, 256>>>();
    k_hist<<<(EE + 255) / 256, 256>>>(dst);
    k_scan1<<<NB_SCAN, 256>>>();
    k_scan2<<<1, 256>>>();
    k_scan3<<<(NN + 255) / 256, 256>>>();
    k_fill<<<(EE + 255) / 256, 256>>>(src, dst);

    const float* hin = x;
    for (int l = 0; l < 7; l++) {
        k_agg<<<(NN * 32 + 255) / 256, 256>>>(hin);
        k_gemm64<false, false><<<(NN + 63) / 64, 256>>>(zp, W1 + (size_t)l * DD * DD,
                                                        b1 + l * DD, t1p);
        k_stats<<<512, 256>>>(t1p);
        k_bnfin<<<1, 128>>>(gamma + l * DD, beta + l * DD);
        k_gemm64<true, true><<<(NN + 63) / 64, 256>>>(t1p, W2 + (size_t)l * DD * DD,
                                                      b2 + l * DD, hp);
        k_readout<<<GG, 256>>>(hp, l);
        hin = hp;
    }
    k_gemm_mlp<<<dim3(FF / 128, GG / 32), 256>>>(featp, Wl1, bl1, feat2p);
    k_head<<<GG, 256>>>(Wl2, bl2, out);
}